// round 9
// baseline (speedup 1.0000x reference)
#include <cuda_runtime.h>

// ChronoRotationTransflormation: per-row normalized complex inner product.
// Inputs: head_real, head_imag, rel_real, rel_imag, tail_real, tail_imag
// all float32 [8192, 2048]. Output: float32 [8192].
//
// R5: warp-per-row layout (no __syncthreads, no smem reduction) + __ldcs
// streaming loads (evict-first; zero reuse so don't pollute L2).

#define D 2048
#define DV (D / 4)              // 512 float4 per row
#define THREADS 256
#define WARPS_PER_CTA (THREADS / 32)
#define F4_PER_LANE (DV / 32)   // 16 float4 per lane per array

__global__ __launch_bounds__(THREADS)
void chrono_rot_kernel(const float4* __restrict__ hr,
                       const float4* __restrict__ hi,
                       const float4* __restrict__ rr,
                       const float4* __restrict__ ri,
                       const float4* __restrict__ tr,
                       const float4* __restrict__ ti,
                       float* __restrict__ out)
{
    const int wid = threadIdx.x >> 5;
    const int lid = threadIdx.x & 31;
    const int row = blockIdx.x * WARPS_PER_CTA + wid;
    const long long base = (long long)row * DV + lid;

    float ab = 0.f, aa = 0.f, bb = 0.f;

    // 16 strided float4 per lane per array; unroll 4 -> 24 LDG.128 in flight
    // per thread batch, streaming (evict-first) since there is zero reuse.
    #pragma unroll 4
    for (int it = 0; it < F4_PER_LANE; ++it) {
        const long long idx = base + (long long)it * 32;
        const float4 HR = __ldcs(hr + idx);
        const float4 HI = __ldcs(hi + idx);
        const float4 RR = __ldcs(rr + idx);
        const float4 RI = __ldcs(ri + idx);
        const float4 TR = __ldcs(tr + idx);
        const float4 TI = __ldcs(ti + idx);

        #pragma unroll
        for (int k = 0; k < 4; ++k) {
            const float h_r = (&HR.x)[k], h_i = (&HI.x)[k];
            const float r_r = (&RR.x)[k], r_i = (&RI.x)[k];
            const float t_r = (&TR.x)[k], t_i = (&TI.x)[k];
            const float rot_r = h_r * r_r - h_i * r_i;
            const float rot_i = -(h_i * r_r + h_r * r_i);
            ab = fmaf(rot_r, t_r, fmaf(rot_i, t_i, ab));
            aa = fmaf(rot_r, rot_r, fmaf(rot_i, rot_i, aa));
            bb = fmaf(t_r, t_r, fmaf(t_i, t_i, bb));
        }
    }

    // Warp butterfly reduction — the only synchronization in the kernel.
    #pragma unroll
    for (int off = 16; off > 0; off >>= 1) {
        ab += __shfl_xor_sync(0xFFFFFFFFu, ab, off);
        aa += __shfl_xor_sync(0xFFFFFFFFu, aa, off);
        bb += __shfl_xor_sync(0xFFFFFFFFu, bb, off);
    }

    if (lid == 0)
        out[row] = ab / sqrtf(aa * bb);
}

extern "C" void kernel_launch(void* const* d_in, const int* in_sizes, int n_in,
                              void* d_out, int out_size)
{
    const float4* hr = (const float4*)d_in[0];
    const float4* hi = (const float4*)d_in[1];
    const float4* rr = (const float4*)d_in[2];
    const float4* ri = (const float4*)d_in[3];
    const float4* tr = (const float4*)d_in[4];
    const float4* ti = (const float4*)d_in[5];
    float* out = (float*)d_out;

    const int rows = out_size;  // 8192
    chrono_rot_kernel<<<rows / WARPS_PER_CTA, THREADS>>>(hr, hi, rr, ri, tr, ti, out);
}

// round 10
// speedup vs baseline: 1.1152x; 1.1152x over previous
#include <cuda_runtime.h>

// ChronoRotationTransflormation: per-row normalized complex inner product.
// Inputs: head_real, head_imag, rel_real, rel_imag, tail_real, tail_imag
// all float32 [8192, 2048]. Output: float32 [8192].
//
// R9: CTA-per-row, 512 threads, ONE float4 per thread per array (6 LDG.128,
// all front-batched, minimal regs -> high occupancy). __ldcs streaming.

#define D 2048
#define DV (D / 4)          // 512 float4 per row
#define THREADS 512         // one float4 per thread
#define WARPS (THREADS / 32)

__global__ __launch_bounds__(THREADS)
void chrono_rot_kernel(const float4* __restrict__ hr,
                       const float4* __restrict__ hi,
                       const float4* __restrict__ rr,
                       const float4* __restrict__ ri,
                       const float4* __restrict__ tr,
                       const float4* __restrict__ ti,
                       float* __restrict__ out)
{
    const long long idx = (long long)blockIdx.x * DV + threadIdx.x;

    // 6 independent streaming loads, issued back-to-back at CTA start.
    const float4 HR = __ldcs(hr + idx);
    const float4 HI = __ldcs(hi + idx);
    const float4 RR = __ldcs(rr + idx);
    const float4 RI = __ldcs(ri + idx);
    const float4 TR = __ldcs(tr + idx);
    const float4 TI = __ldcs(ti + idx);

    float ab = 0.f, aa = 0.f, bb = 0.f;
    #pragma unroll
    for (int k = 0; k < 4; ++k) {
        const float h_r = (&HR.x)[k], h_i = (&HI.x)[k];
        const float r_r = (&RR.x)[k], r_i = (&RI.x)[k];
        const float t_r = (&TR.x)[k], t_i = (&TI.x)[k];
        const float rot_r = h_r * r_r - h_i * r_i;
        const float rot_i = -(h_i * r_r + h_r * r_i);
        ab = fmaf(rot_r, t_r, fmaf(rot_i, t_i, ab));
        aa = fmaf(rot_r, rot_r, fmaf(rot_i, rot_i, aa));
        bb = fmaf(t_r, t_r, fmaf(t_i, t_i, bb));
    }

    // Warp butterfly reduction.
    #pragma unroll
    for (int off = 16; off > 0; off >>= 1) {
        ab += __shfl_xor_sync(0xFFFFFFFFu, ab, off);
        aa += __shfl_xor_sync(0xFFFFFFFFu, aa, off);
        bb += __shfl_xor_sync(0xFFFFFFFFu, bb, off);
    }

    __shared__ float s_ab[WARPS], s_aa[WARPS], s_bb[WARPS];
    const int wid = threadIdx.x >> 5;
    const int lid = threadIdx.x & 31;
    if (lid == 0) {
        s_ab[wid] = ab;
        s_aa[wid] = aa;
        s_bb[wid] = bb;
    }
    __syncthreads();

    // Final reduction by warp 0: 16 partials live in lanes 0..15.
    if (wid == 0) {
        float tab = (lid < WARPS) ? s_ab[lid] : 0.f;
        float taa = (lid < WARPS) ? s_aa[lid] : 0.f;
        float tbb = (lid < WARPS) ? s_bb[lid] : 0.f;
        #pragma unroll
        for (int off = 8; off > 0; off >>= 1) {
            tab += __shfl_xor_sync(0xFFFFFFFFu, tab, off);
            taa += __shfl_xor_sync(0xFFFFFFFFu, taa, off);
            tbb += __shfl_xor_sync(0xFFFFFFFFu, tbb, off);
        }
        if (lid == 0)
            out[blockIdx.x] = tab / sqrtf(taa * tbb);
    }
}

extern "C" void kernel_launch(void* const* d_in, const int* in_sizes, int n_in,
                              void* d_out, int out_size)
{
    const float4* hr = (const float4*)d_in[0];
    const float4* hi = (const float4*)d_in[1];
    const float4* rr = (const float4*)d_in[2];
    const float4* ri = (const float4*)d_in[3];
    const float4* tr = (const float4*)d_in[4];
    const float4* ti = (const float4*)d_in[5];
    float* out = (float*)d_out;

    const int rows = out_size;  // 8192
    chrono_rot_kernel<<<rows, THREADS>>>(hr, hi, rr, ri, tr, ti, out);
}